// round 7
// baseline (speedup 1.0000x reference)
#include <cuda_runtime.h>
#include <cstdint>

// ---------------------------------------------------------------------------
// UniformAssigner with 16x16 spatial binning (64-px cells).
//  k_build  : one block. Clears per-gt top-4 slots; builds per-cell gt lists
//             (window = cell extended by max anchor half-extent 68 + gt size).
//  k_main   : per anchor: fast path scans only its cell's gt list (~9 gts);
//             anchors violating the binning preconditions scan all M.
//             Gate (conservative 0.12) -> exact reference IoU -> ign flag +
//             lock-free per-gt top-4 (atomicMax cascade on (iou<<32|idx)).
//  k_scatter: <=4M entries -> atomicMax gt_id onto assigned[anchor].
//  k_final  : labels + bboxes. out[0:N]=labels, out[N:5N]=bboxes.
// ---------------------------------------------------------------------------

#define MAXM   512        // supported M (M = 128 here)
#define CELLS  256        // 16 x 16
#define STRIDE 512        // per-cell list capacity (>= MAXM, always safe)

__device__ unsigned long long g_topk[MAXM * 4];   // packed keys, 0 = empty
__device__ int            g_assigned[1u << 20];   // baseline 0/-1, then gt ids
__device__ unsigned short g_list[CELLS * STRIDE]; // per-cell gt indices
__device__ int            g_cnt[CELLS];

// ---------------------------------------------------------------- build -----
__global__ void k_build(const float4* __restrict__ gts, int M) {
    __shared__ float4 sb[MAXM];
    for (int g = threadIdx.x; g < M; g += blockDim.x) sb[g] = gts[g];
    // clear all top-k slots (MAXM*4 = 2048)
    for (int s = threadIdx.x; s < MAXM * 4; s += blockDim.x) g_topk[s] = 0ULL;
    __syncthreads();

    int cell = threadIdx.x;            // 256 threads, one per cell
    if (cell >= CELLS) return;
    float cx0 = (float)((cell & 15) * 64);
    float cy0 = (float)((cell >> 4) * 64);
    // Anchor on fast path: center in this cell, half-extent <= 68.
    //  => anchor x-range subset of (cx0-68, cx0+64+68).  Overlap needs
    //  gt.x1 < cx0+132  and  gt.x2 > cx0-68  (same in y).  Inclusive margins
    //  only ever ADD gts (never drop), so <=/>= are safe.
    int c = 0;
    for (int g = 0; g < M; g++) {
        float4 b = sb[g];
        bool ok = (b.x <= cx0 + 132.0f) & (b.z >= cx0 - 68.0f) &
                  (b.y <= cy0 + 132.0f) & (b.w >= cy0 - 68.0f);
        if (ok) g_list[cell * STRIDE + c++] = (unsigned short)g;
    }
    g_cnt[cell] = c;
}

// ---------------------------------------------------------------- main ------
__device__ __forceinline__ void topk_insert(int g, float iou, unsigned int idx) {
    unsigned long long key =
        ((unsigned long long)__float_as_uint(iou) << 32) | idx;
    unsigned long long* slots = &g_topk[g * 4];
    // slots are monotone non-decreasing & pairwise sorted; a stale read of
    // slot[3] can only be <= current, so skipping on key<=read is safe.
    unsigned long long s3;
    asm volatile("ld.global.cg.u64 %0, [%1];" : "=l"(s3) : "l"(slots + 3));
    if (key > s3) {
#pragma unroll
        for (int s = 0; s < 4; s++) {
            unsigned long long prev = atomicMax(&slots[s], key);
            if (prev == 0ULL) break;        // landed in an empty slot
            key = prev < key ? prev : key;  // push displaced smaller key down
        }
    }
}

__global__ void __launch_bounds__(256)
k_main(const float4* __restrict__ anchors, const float4* __restrict__ gts,
       int N, int M) {
    __shared__ float4 sbox[MAXM];
    __shared__ float  sarea[MAXM];   // exact gt area (union)
    __shared__ float  sthr[MAXM];    // 0.12 * gt area (gate)
    for (int g = threadIdx.x; g < M; g += blockDim.x) {
        float4 b  = gts[g];
        float  ar = (b.z - b.x) * (b.w - b.y);
        sbox[g]  = b;
        sarea[g] = ar;
        sthr[g]  = 0.12f * ar;
    }
    __syncthreads();

    const int i = blockIdx.x * blockDim.x + threadIdx.x;
    if (i >= N) return;

    const float4 a     = anchors[i];
    const float  areaA = (a.z - a.x) * (a.w - a.y);
    const float  tA    = 0.12f * areaA;

    // fast path preconditions (exactly what k_build's window assumes)
    const float cx = 0.5f * (a.x + a.z);
    const float cy = 0.5f * (a.y + a.w);
    const bool fast = ((a.z - a.x) <= 136.0f) & ((a.w - a.y) <= 136.0f) &
                      (cx >= 0.0f) & (cx < 1024.0f) &
                      (cy >= 0.0f) & (cy < 1024.0f);

    int cell = (int)(cy * 0.015625f) * 16 + (int)(cx * 0.015625f);
    cell = cell < 0 ? 0 : (cell > CELLS - 1 ? CELLS - 1 : cell);
    const int cnt = fast ? g_cnt[cell] : M;
    const unsigned short* lst = &g_list[cell * STRIDE];

    int ign = 0;
    for (int j = 0; j < cnt; j++) {
        int g = fast ? (int)lst[j] : j;
        float4 b = sbox[g];
        float iw    = fminf(a.z, b.z) - fmaxf(a.x, b.x);
        float ih    = fminf(a.w, b.w) - fmaxf(a.y, b.y);
        float inter = fmaxf(iw, 0.0f) * fmaxf(ih, 0.0f);
        // conservative gate: true iou >= 0.15 => inter >= 0.1304*(aA+aB) > gate
        if (inter >= tA + sthr[g]) {
            float uni = (areaA + sarea[g]) - inter;
            float iou = inter / fmaxf(uni, 1e-7f);   // exact ref expression
            ign |= (iou >= 0.7f);
            if (iou >= 0.15f) topk_insert(g, iou, (unsigned int)i);
        }
    }

    g_assigned[i] = ign ? -1 : 0;
}

// ------------------------------------------------------------- scatter ------
__global__ void k_scatter(int M) {
    int i = blockIdx.x * blockDim.x + threadIdx.x;
    if (i >= M * 4) return;
    unsigned long long key = g_topk[i];
    if (key == 0ULL) return;
    float iou = __uint_as_float((unsigned int)(key >> 32));
    if (iou >= 0.15f) {
        int idx = (int)(key & 0xffffffffULL);
        atomicMax(&g_assigned[idx], i / 4 + 1);
    }
}

// ------------------------------------------------------------ finalize ------
__global__ void __launch_bounds__(256)
k_final(const float4* __restrict__ gts, const int* __restrict__ labels,
        float* __restrict__ out, int N) {
    const int i = blockIdx.x * blockDim.x + threadIdx.x;
    if (i >= N) return;
    int a = g_assigned[i];
    float  lab;
    float4 bb;
    if (a > 0) {
        lab = (float)labels[a - 1];
        bb  = gts[a - 1];
    } else {
        lab = (a == 0) ? 0.0f : -1.0f;
        bb  = make_float4(-1.0f, -1.0f, -1.0f, -1.0f);
    }
    out[i] = lab;
    if ((N & 3) == 0) {
        reinterpret_cast<float4*>(out + N)[i] = bb;   // out+N is 16B-aligned
    } else {
        float* p = out + N + 4 * i;
        p[0] = bb.x; p[1] = bb.y; p[2] = bb.z; p[3] = bb.w;
    }
}

// --------------------------------------------------------------------------
extern "C" void kernel_launch(void* const* d_in, const int* in_sizes, int n_in,
                              void* d_out, int out_size) {
    const float4* anchors = (const float4*)d_in[0];
    const float4* gts     = (const float4*)d_in[1];
    const int*    labels  = (const int*)d_in[2];
    int N = in_sizes[0] / 4;
    int M = in_sizes[1] / 4;
    float* out = (float*)d_out;

    k_build<<<1, 256>>>(gts, M);
    k_main<<<(N + 255) / 256, 256>>>(anchors, gts, N, M);
    k_scatter<<<(M * 4 + 255) / 256, 256>>>(M);
    k_final<<<(N + 255) / 256, 256>>>(gts, labels, out, N);
}